// round 15
// baseline (speedup 1.0000x reference)
#include <cuda_runtime.h>
#include <cuda_fp16.h>
#include <cstdint>

// ---------------- problem constants ----------------
#define NROWS 8192
#define DK    512

// ---------------- GEMM tile config ----------------
#define BM 128
#define BN 128
#define BK 64
#define KITERS (DK / BK)                      // 8
#define NTILES ((NROWS / BM) * (NROWS / BN))  // 4096
#define NSTAGE 3
#define A_STAGE_BYTES (BM * BK * 2)           // 16384
#define B_STAGE_BYTES (BN * BK * 2)           // 16384
#define STAGE_BYTES (A_STAGE_BYTES + B_STAGE_BYTES)   // 32768
#define SMEM_TOTAL (NSTAGE * STAGE_BYTES)     // 98304

// ---------------- device scratch (no allocs allowed) ----------------
__device__ __half g_A2[(size_t)NROWS * DK];
__device__ __half g_B2[(size_t)NROWS * DK];
__device__ float  g_ssq[NROWS];
__device__ float  g_tsq[NROWS];

// ---------------- PTX helpers (all baseline compute_103-legal) ----------------
__device__ __forceinline__ uint32_t smem_u32(const void* p) {
    uint32_t a;
    asm("{ .reg .u64 t; cvta.to.shared.u64 t, %1; cvt.u32.u64 %0, t; }"
        : "=r"(a) : "l"(p));
    return a;
}

__device__ __forceinline__ void cp_async16(uint32_t dst, const void* src) {
    asm volatile("cp.async.cg.shared.global [%0], [%1], 16;"
                 :: "r"(dst), "l"(src) : "memory");
}

__device__ __forceinline__ void ldmx4(uint32_t& r0, uint32_t& r1, uint32_t& r2,
                                      uint32_t& r3, uint32_t addr) {
    asm volatile("ldmatrix.sync.aligned.m8n8.x4.shared.b16 {%0,%1,%2,%3}, [%4];"
                 : "=r"(r0), "=r"(r1), "=r"(r2), "=r"(r3) : "r"(addr));
}

__device__ __forceinline__ void mma16816(float* c, const uint32_t* a,
                                         const uint32_t* b) {
    asm volatile(
        "mma.sync.aligned.m16n8k16.row.col.f32.f16.f16.f32 "
        "{%0,%1,%2,%3}, {%4,%5,%6,%7}, {%8,%9}, {%0,%1,%2,%3};"
        : "+f"(c[0]), "+f"(c[1]), "+f"(c[2]), "+f"(c[3])
        : "r"(a[0]), "r"(a[1]), "r"(a[2]), "r"(a[3]), "r"(b[0]), "r"(b[1]));
}

// ---------------- prep: fp32 -> fp16 + row sum of squares ----------------
__global__ void __launch_bounds__(128)
prep2_kernel(const float* __restrict__ s, const float* __restrict__ t,
             __half* __restrict__ ah, __half* __restrict__ bh,
             float* __restrict__ ssq, float* __restrict__ tsq) {
    int b = blockIdx.x;
    int row = b & (NROWS - 1);
    bool isT = b >= NROWS;
    const float* in = isT ? t : s;
    __half* oh = isT ? bh : ah;
    float* sq = isT ? tsq : ssq;

    float4 v = ((const float4*)(in + (size_t)row * DK))[threadIdx.x];
    float acc = v.x * v.x + v.y * v.y + v.z * v.z + v.w * v.w;

    __half2 h0 = __floats2half2_rn(v.x, v.y);
    __half2 h1 = __floats2half2_rn(v.z, v.w);
    uint2 pk;
    pk.x = *(uint32_t*)&h0;
    pk.y = *(uint32_t*)&h1;
    ((uint2*)(oh + (size_t)row * DK))[threadIdx.x] = pk;

    #pragma unroll
    for (int off = 16; off > 0; off >>= 1)
        acc += __shfl_xor_sync(0xFFFFFFFFu, acc, off);
    __shared__ float ws[4];
    if ((threadIdx.x & 31) == 0) ws[threadIdx.x >> 5] = acc;
    __syncthreads();
    if (threadIdx.x == 0) sq[row] = ws[0] + ws[1] + ws[2] + ws[3];
}

// ---------------- persistent GEMM + fused epilogue (R6 inner body) ----------
__global__ void __launch_bounds__(256, 2)
dist_gemm_kernel(float* __restrict__ dout) {
    extern __shared__ __align__(1024) char smem[];
    uint32_t sb = smem_u32(smem);
    const int tid = threadIdx.x;
    const int wid = tid >> 5;
    const int lid = tid & 31;

    const int bid = blockIdx.x;
    const int gsz = gridDim.x;
    const int my_ntiles = (NTILES - bid + gsz - 1) / gsz;

    // warp layout: 4 (M) x 2 (N); warp tile 32 (M) x 64 (N)
    const int wm = wid >> 1;
    const int wn = wid & 1;

    // ---- global-stream stage loader; ls = global k-step index ----
    // stage = ls % NSTAGE; tile = bid + (ls / KITERS) * gsz
    auto issue_load = [&](int ls) {
        int tl = ls >> 3;                       // KITERS == 8
        if (tl < my_ntiles) {
            int tile = bid + tl * gsz;
            int lm0 = (tile >> 6) * BM;         // 64 n-tiles per m-row
            int ln0 = (tile & 63) * BN;
            int kc0 = (ls & 7) * BK;
            const __half* lgA = g_A2 + (size_t)lm0 * DK;
            const __half* lgB = g_B2 + (size_t)ln0 * DK;
            uint32_t base = sb + (uint32_t)(ls % NSTAGE) * STAGE_BYTES;
            #pragma unroll
            for (int it = 0; it < 8; it++) {
                int v = tid + it * 256;
                bool isA = v < 1024;
                int u = v & 1023;
                int row = u >> 3;
                int vc = u & 7;
                uint32_t off = (uint32_t)(row * 128 + vc * 16);
                uint32_t sw = off ^ ((uint32_t)(row & 7) << 4);
                uint32_t dst = base + (isA ? 0u : (uint32_t)A_STAGE_BYTES) + sw;
                const __half* src =
                    (isA ? lgA : lgB) + (size_t)row * DK + kc0 + vc * 8;
                cp_async16(dst, src);
            }
        }
        asm volatile("cp.async.commit_group;" ::: "memory");
    };

    // ---- per-lane ldmatrix base addresses (tile-independent smem offsets) ----
    const int jj = lid >> 3;
    const int jr = lid & 7;
    const int a_row_in_tile = ((jj & 1) << 3) + jr;
    const uint32_t a_kadd = (uint32_t)((jj >> 1) << 4);
    const int b_row_in_tile = ((jj >> 1) << 3) + jr;
    const uint32_t b_kadd = (uint32_t)((jj & 1) << 4);

    uint32_t aAddr[2];
    #pragma unroll
    for (int mi = 0; mi < 2; mi++) {
        int row = wm * 32 + mi * 16 + a_row_in_tile;
        aAddr[mi] = (uint32_t)(row * 128) + (a_kadd ^ ((uint32_t)(row & 7) << 4));
    }
    uint32_t bAddr[4];
    #pragma unroll
    for (int p = 0; p < 4; p++) {
        int row = wn * 64 + p * 16 + b_row_in_tile;
        bAddr[p] = (uint32_t)(row * 128) + (b_kadd ^ ((uint32_t)(row & 7) << 4)) +
                   (uint32_t)A_STAGE_BYTES;
    }

    // ---- pipeline prologue: first two stage loads of the stream ----
    issue_load(0);
    issue_load(1);

    int st = 0;          // stage of current global step
    int gs = 0;          // global step counter

    for (int t = 0; t < my_ntiles; t++) {
        int tile = bid + t * gsz;
        const int m0 = (tile >> 6) * BM;
        const int n0 = (tile & 63) * BN;

        float acc[2][8][4];
        #pragma unroll
        for (int mi = 0; mi < 2; mi++)
            #pragma unroll
            for (int ni = 0; ni < 8; ni++)
                #pragma unroll
                for (int c = 0; c < 4; c++) acc[mi][ni][c] = 0.0f;

        for (int ki = 0; ki < KITERS; ki++, gs++) {
            asm volatile("cp.async.wait_group 1;" ::: "memory");
            __syncthreads();
            issue_load(gs + 2);

            uint32_t stageBase = sb + (uint32_t)st * STAGE_BYTES;

            #pragma unroll
            for (int ks = 0; ks < BK / 16; ks++) {
                const uint32_t kb = (uint32_t)(ks * 32);
                uint32_t af[2][4];
                #pragma unroll
                for (int mi = 0; mi < 2; mi++)
                    ldmx4(af[mi][0], af[mi][1], af[mi][2], af[mi][3],
                          stageBase + (aAddr[mi] ^ kb));
                uint32_t bf[8][2];
                #pragma unroll
                for (int p = 0; p < 4; p++) {
                    uint32_t r0, r1, r2, r3;
                    ldmx4(r0, r1, r2, r3, stageBase + (bAddr[p] ^ kb));
                    bf[2 * p][0] = r0; bf[2 * p][1] = r1;
                    bf[2 * p + 1][0] = r2; bf[2 * p + 1][1] = r3;
                }
                #pragma unroll
                for (int mi = 0; mi < 2; mi++)
                    #pragma unroll
                    for (int ni = 0; ni < 8; ni++)
                        mma16816(acc[mi][ni], af[mi], bf[ni]);
            }

            st++; if (st >= NSTAGE) st = 0;
        }

        // ----- epilogue for this tile: out = ssq[row] + tsq[col] - 2*acc ----
        // (touches no smem; next tile's cp.asyncs are already in flight)
        const int rbase = m0 + wm * 32 + (lid >> 2);
        const int cbase = n0 + wn * 64 + (lid & 3) * 2;

        #pragma unroll
        for (int mi = 0; mi < 2; mi++) {
            int r_lo = rbase + mi * 16;
            int r_hi = r_lo + 8;
            float sq_lo = g_ssq[r_lo];
            float sq_hi = g_ssq[r_hi];
            float* out_lo = dout + (size_t)r_lo * NROWS;
            float* out_hi = dout + (size_t)r_hi * NROWS;
            #pragma unroll
            for (int ni = 0; ni < 8; ni++) {
                int col = cbase + ni * 8;
                float tq0 = g_tsq[col];
                float tq1 = g_tsq[col + 1];
                float2 vlo, vhi;
                vlo.x = sq_lo + tq0 - 2.0f * acc[mi][ni][0];
                vlo.y = sq_lo + tq1 - 2.0f * acc[mi][ni][1];
                vhi.x = sq_hi + tq0 - 2.0f * acc[mi][ni][2];
                vhi.y = sq_hi + tq1 - 2.0f * acc[mi][ni][3];
                *(float2*)(out_lo + col) = vlo;
                *(float2*)(out_hi + col) = vhi;
            }
        }
    }
}

// ---------------- launch ----------------
extern "C" void kernel_launch(void* const* d_in, const int* in_sizes, int n_in,
                              void* d_out, int out_size) {
    const float* s = (const float*)d_in[0];
    const float* t = (const float*)d_in[1];
    float* out = (float*)d_out;

    cudaFuncSetAttribute(dist_gemm_kernel,
                         cudaFuncAttributeMaxDynamicSharedMemorySize, SMEM_TOTAL);

    int nsm = 0;
    cudaDeviceGetAttribute(&nsm, cudaDevAttrMultiProcessorCount, 0);
    if (nsm <= 0) nsm = 148;
    int grid = 2 * nsm;                 // 2 CTAs resident per SM
    if (grid > NTILES) grid = NTILES;

    __half* a2;
    __half* b2;
    float* ssq;
    float* tsq;
    cudaGetSymbolAddress((void**)&a2, g_A2);
    cudaGetSymbolAddress((void**)&b2, g_B2);
    cudaGetSymbolAddress((void**)&ssq, g_ssq);
    cudaGetSymbolAddress((void**)&tsq, g_tsq);

    prep2_kernel<<<2 * NROWS, 128>>>(s, t, a2, b2, ssq, tsq);

    dist_gemm_kernel<<<grid, 256, SMEM_TOTAL>>>(out);
}

// round 17
// speedup vs baseline: 1.6148x; 1.6148x over previous
#include <cuda_runtime.h>
#include <cuda_fp16.h>
#include <cstdint>

// ---------------- problem constants ----------------
#define NROWS 8192
#define DK    512

// ---------------- GEMM tile config ----------------
#define BM 128
#define BN 128
#define BK 64
#define KITERS (DK / BK)                      // 8
#define NSTAGE 3
#define A_STAGE_BYTES (BM * BK * 2)           // 16384
#define B_STAGE_BYTES (BN * BK * 2)           // 16384
#define STAGE_BYTES (A_STAGE_BYTES + B_STAGE_BYTES)   // 32768
#define SMEM_TOTAL (NSTAGE * STAGE_BYTES)     // 98304

// ---------------- device scratch (no allocs allowed) ----------------
__device__ __half g_A2[(size_t)NROWS * DK];
__device__ __half g_B2[(size_t)NROWS * DK];
__device__ float  g_ssq[NROWS];
__device__ float  g_tsq[NROWS];

// ---------------- PTX helpers (all baseline compute_103-legal) ----------------
__device__ __forceinline__ uint32_t smem_u32(const void* p) {
    uint32_t a;
    asm("{ .reg .u64 t; cvta.to.shared.u64 t, %1; cvt.u32.u64 %0, t; }"
        : "=r"(a) : "l"(p));
    return a;
}

__device__ __forceinline__ void cp_async16(uint32_t dst, const void* src) {
    asm volatile("cp.async.cg.shared.global [%0], [%1], 16;"
                 :: "r"(dst), "l"(src) : "memory");
}

__device__ __forceinline__ void ldmx4(uint32_t& r0, uint32_t& r1, uint32_t& r2,
                                      uint32_t& r3, uint32_t addr) {
    asm volatile("ldmatrix.sync.aligned.m8n8.x4.shared.b16 {%0,%1,%2,%3}, [%4];"
                 : "=r"(r0), "=r"(r1), "=r"(r2), "=r"(r3) : "r"(addr));
}

// fp16 accumulator variant: 2 c-registers (packed half2) instead of 4 floats
__device__ __forceinline__ void mma16816_f16(uint32_t* c, const uint32_t* a,
                                             const uint32_t* b) {
    asm volatile(
        "mma.sync.aligned.m16n8k16.row.col.f16.f16.f16.f16 "
        "{%0,%1}, {%2,%3,%4,%5}, {%6,%7}, {%0,%1};"
        : "+r"(c[0]), "+r"(c[1])
        : "r"(a[0]), "r"(a[1]), "r"(a[2]), "r"(a[3]), "r"(b[0]), "r"(b[1]));
}

// ---------------- prep: fp32 -> fp16 + row sum of squares ----------------
__global__ void __launch_bounds__(128)
prep2_kernel(const float* __restrict__ s, const float* __restrict__ t,
             __half* __restrict__ ah, __half* __restrict__ bh,
             float* __restrict__ ssq, float* __restrict__ tsq) {
    int b = blockIdx.x;
    int row = b & (NROWS - 1);
    bool isT = b >= NROWS;
    const float* in = isT ? t : s;
    __half* oh = isT ? bh : ah;
    float* sq = isT ? tsq : ssq;

    float4 v = ((const float4*)(in + (size_t)row * DK))[threadIdx.x];
    float acc = v.x * v.x + v.y * v.y + v.z * v.z + v.w * v.w;

    __half2 h0 = __floats2half2_rn(v.x, v.y);
    __half2 h1 = __floats2half2_rn(v.z, v.w);
    uint2 pk;
    pk.x = *(uint32_t*)&h0;
    pk.y = *(uint32_t*)&h1;
    ((uint2*)(oh + (size_t)row * DK))[threadIdx.x] = pk;

    #pragma unroll
    for (int off = 16; off > 0; off >>= 1)
        acc += __shfl_xor_sync(0xFFFFFFFFu, acc, off);
    __shared__ float ws[4];
    if ((threadIdx.x & 31) == 0) ws[threadIdx.x >> 5] = acc;
    __syncthreads();
    if (threadIdx.x == 0) sq[row] = ws[0] + ws[1] + ws[2] + ws[3];
}

// ---------------- GEMM + fused epilogue (R6 structure, fp16 acc) ------------
__global__ void __launch_bounds__(256, 2)
dist_gemm_kernel(float* __restrict__ dout) {
    extern __shared__ __align__(1024) char smem[];
    uint32_t sb = smem_u32(smem);
    const int tid = threadIdx.x;
    const int wid = tid >> 5;
    const int lid = tid & 31;

    const int m0 = blockIdx.y * BM;
    const int n0 = blockIdx.x * BN;
    const __half* gA = g_A2 + (size_t)m0 * DK;
    const __half* gB = g_B2 + (size_t)n0 * DK;

    // warp layout: 4 (M) x 2 (N); warp tile 32 (M) x 64 (N)
    const int wm = wid >> 1;
    const int wn = wid & 1;

    // ---- stage loader: 2048 x 16B vectors (A: 1024, B: 1024) ----
    auto load_stage = [&](int st, int kc0) {
        uint32_t base = sb + st * STAGE_BYTES;
        #pragma unroll
        for (int it = 0; it < 8; it++) {
            int v = tid + it * 256;
            bool isA = v < 1024;
            int u = v & 1023;
            int row = u >> 3;
            int vc = u & 7;
            uint32_t off = (uint32_t)(row * 128 + vc * 16);
            uint32_t sw = off ^ ((uint32_t)(row & 7) << 4);
            uint32_t dst = base + (isA ? 0u : (uint32_t)A_STAGE_BYTES) + sw;
            const __half* src = (isA ? gA : gB) + (size_t)row * DK + kc0 + vc * 8;
            cp_async16(dst, src);
        }
        asm volatile("cp.async.commit_group;" ::: "memory");
    };

    // ---- per-lane ldmatrix base addresses (XOR-composable k offset) ----
    const int jj = lid >> 3;
    const int jr = lid & 7;
    const int a_row_in_tile = ((jj & 1) << 3) + jr;
    const uint32_t a_kadd = (uint32_t)((jj >> 1) << 4);
    const int b_row_in_tile = ((jj >> 1) << 3) + jr;
    const uint32_t b_kadd = (uint32_t)((jj & 1) << 4);

    uint32_t aAddr[2];
    #pragma unroll
    for (int mi = 0; mi < 2; mi++) {
        int row = wm * 32 + mi * 16 + a_row_in_tile;
        aAddr[mi] = (uint32_t)(row * 128) + (a_kadd ^ ((uint32_t)(row & 7) << 4));
    }
    uint32_t bAddr[4];
    #pragma unroll
    for (int p = 0; p < 4; p++) {
        int row = wn * 64 + p * 16 + b_row_in_tile;
        bAddr[p] = (uint32_t)(row * 128) + (b_kadd ^ ((uint32_t)(row & 7) << 4)) +
                   (uint32_t)A_STAGE_BYTES;
    }

    // fp16 accumulators: [mi][ni][2] packed half2 (c0: row lo, c1: row hi)
    uint32_t acc[2][8][2];
    #pragma unroll
    for (int mi = 0; mi < 2; mi++)
        #pragma unroll
        for (int ni = 0; ni < 8; ni++) {
            acc[mi][ni][0] = 0u;
            acc[mi][ni][1] = 0u;
        }

    // ---- 3-stage pipeline prologue ----
    load_stage(0, 0);
    load_stage(1, BK);

    int st = 0;
    for (int ki = 0; ki < KITERS; ki++) {
        if (ki + 1 < KITERS) {
            asm volatile("cp.async.wait_group 1;" ::: "memory");
        } else {
            asm volatile("cp.async.wait_group 0;" ::: "memory");
        }
        __syncthreads();
        if (ki + 2 < KITERS) {
            int nst = st + 2; if (nst >= NSTAGE) nst -= NSTAGE;
            load_stage(nst, (ki + 2) * BK);
        }

        uint32_t stageBase = sb + st * STAGE_BYTES;

        #pragma unroll
        for (int ks = 0; ks < BK / 16; ks++) {
            const uint32_t kb = (uint32_t)(ks * 32);
            uint32_t af[2][4];
            #pragma unroll
            for (int mi = 0; mi < 2; mi++)
                ldmx4(af[mi][0], af[mi][1], af[mi][2], af[mi][3],
                      stageBase + (aAddr[mi] ^ kb));
            uint32_t bf[8][2];
            #pragma unroll
            for (int p = 0; p < 4; p++) {
                uint32_t r0, r1, r2, r3;
                ldmx4(r0, r1, r2, r3, stageBase + (bAddr[p] ^ kb));
                bf[2 * p][0] = r0; bf[2 * p][1] = r1;
                bf[2 * p + 1][0] = r2; bf[2 * p + 1][1] = r3;
            }
            #pragma unroll
            for (int mi = 0; mi < 2; mi++)
                #pragma unroll
                for (int ni = 0; ni < 8; ni++)
                    mma16816_f16(acc[mi][ni], af[mi], bf[ni]);
        }

        st++; if (st >= NSTAGE) st = 0;
    }

    // ----- epilogue: out = ssq[row] + tsq[col] - 2*acc (unpack fp16 acc) ----
    // c0 holds (row = lane>>2, cols (lane&3)*2 + {0,1}); c1 same cols, row+8
    const int rbase = m0 + wm * 32 + (lid >> 2);
    const int cbase = n0 + wn * 64 + (lid & 3) * 2;

    #pragma unroll
    for (int mi = 0; mi < 2; mi++) {
        int r_lo = rbase + mi * 16;
        int r_hi = r_lo + 8;
        float sq_lo = g_ssq[r_lo];
        float sq_hi = g_ssq[r_hi];
        float* out_lo = dout + (size_t)r_lo * NROWS;
        float* out_hi = dout + (size_t)r_hi * NROWS;
        #pragma unroll
        for (int ni = 0; ni < 8; ni++) {
            int col = cbase + ni * 8;
            float tq0 = g_tsq[col];
            float tq1 = g_tsq[col + 1];
            float2 lo = __half22float2(*(__half2*)&acc[mi][ni][0]);
            float2 hi = __half22float2(*(__half2*)&acc[mi][ni][1]);
            float2 vlo, vhi;
            vlo.x = sq_lo + tq0 - 2.0f * lo.x;
            vlo.y = sq_lo + tq1 - 2.0f * lo.y;
            vhi.x = sq_hi + tq0 - 2.0f * hi.x;
            vhi.y = sq_hi + tq1 - 2.0f * hi.y;
            *(float2*)(out_lo + col) = vlo;
            *(float2*)(out_hi + col) = vhi;
        }
    }
}

// ---------------- launch ----------------
extern "C" void kernel_launch(void* const* d_in, const int* in_sizes, int n_in,
                              void* d_out, int out_size) {
    const float* s = (const float*)d_in[0];
    const float* t = (const float*)d_in[1];
    float* out = (float*)d_out;

    cudaFuncSetAttribute(dist_gemm_kernel,
                         cudaFuncAttributeMaxDynamicSharedMemorySize, SMEM_TOTAL);

    __half* a2;
    __half* b2;
    float* ssq;
    float* tsq;
    cudaGetSymbolAddress((void**)&a2, g_A2);
    cudaGetSymbolAddress((void**)&b2, g_B2);
    cudaGetSymbolAddress((void**)&ssq, g_ssq);
    cudaGetSymbolAddress((void**)&tsq, g_tsq);

    prep2_kernel<<<2 * NROWS, 128>>>(s, t, a2, b2, ssq, tsq);

    dim3 grid(NROWS / BN, NROWS / BM);
    dist_gemm_kernel<<<grid, 256, SMEM_TOTAL>>>(out);
}